// round 1
// baseline (speedup 1.0000x reference)
#include <cuda_runtime.h>
#include <cuda_bf16.h>

#define NN 100000
#define NE 1600000
#define NG 64
#define D  128
#define POOL_CHUNK 256

// ---------------- device scratch (no dynamic allocation allowed) ----------------
__device__ float d_hA[NN * D];
__device__ float d_hB[NN * D];
__device__ float d_agg[NN * D];
__device__ float d_agg4[NN * 4];
__device__ int   d_count[NN];
__device__ int   d_rowptr[NN + 1];
__device__ int   d_cursor[NN];
__device__ int   d_csr_src[NE];
__device__ float d_pool_sum[NG * D];
__device__ float d_pool_max[NG * D];
__device__ int   d_pool_cnt[NG];

// ---------------- prep: zero counters / pool accumulators ----------------
__global__ void zero_prep() {
    int i = blockIdx.x * blockDim.x + threadIdx.x;
    int stride = gridDim.x * blockDim.x;
    for (int k = i; k < NN; k += stride) d_count[k] = 0;
    for (int k = i; k < NG * D; k += stride) { d_pool_sum[k] = 0.f; d_pool_max[k] = 0.f; }
    for (int k = i; k < NG; k += stride) d_pool_cnt[k] = 0;
}

// ---------------- CSR build ----------------
__global__ void count_k(const int* __restrict__ dst) {
    int i = blockIdx.x * blockDim.x + threadIdx.x;
    int stride = gridDim.x * blockDim.x;
    for (int e = i; e < NE; e += stride) atomicAdd(&d_count[dst[e]], 1);
}

__global__ void scan_rowptr() {
    __shared__ int buf[1024];
    __shared__ int carry_s;
    int t = threadIdx.x;
    if (t == 0) carry_s = 0;
    __syncthreads();
    for (int base = 0; base < NN; base += 1024) {
        int idx = base + t;
        int v = (idx < NN) ? d_count[idx] : 0;
        buf[t] = v;
        __syncthreads();
        for (int off = 1; off < 1024; off <<= 1) {
            int add = (t >= off) ? buf[t - off] : 0;
            __syncthreads();
            buf[t] += add;
            __syncthreads();
        }
        if (idx < NN) d_rowptr[idx] = carry_s + buf[t] - v;  // exclusive scan
        __syncthreads();
        if (t == 1023) carry_s += buf[1023];
        __syncthreads();
    }
    if (t == 0) d_rowptr[NN] = carry_s;
}

__global__ void copy_cursor() {
    int i = blockIdx.x * blockDim.x + threadIdx.x;
    int stride = gridDim.x * blockDim.x;
    for (int k = i; k < NN; k += stride) d_cursor[k] = d_rowptr[k];
}

__global__ void scatter_k(const int* __restrict__ src, const int* __restrict__ dst) {
    int i = blockIdx.x * blockDim.x + threadIdx.x;
    int stride = gridDim.x * blockDim.x;
    for (int e = i; e < NE; e += stride) {
        int pos = atomicAdd(&d_cursor[dst[e]], 1);
        d_csr_src[pos] = src[e];
    }
}

// ---------------- layer 1: aggregate 4-dim input features ----------------
__global__ void agg4_k(const float* __restrict__ x) {
    int n = blockIdx.x * blockDim.x + threadIdx.x;
    if (n >= NN) return;
    int beg = d_rowptr[n], end = d_rowptr[n + 1];
    const float4* xv = (const float4*)x;
    float4 a = {0.f, 0.f, 0.f, 0.f};
    int i = beg;
    for (; i + 3 < end; i += 4) {
        int s0 = d_csr_src[i], s1 = d_csr_src[i + 1], s2 = d_csr_src[i + 2], s3 = d_csr_src[i + 3];
        float4 v0 = xv[s0], v1 = xv[s1], v2 = xv[s2], v3 = xv[s3];
        a.x += v0.x + v1.x + v2.x + v3.x;
        a.y += v0.y + v1.y + v2.y + v3.y;
        a.z += v0.z + v1.z + v2.z + v3.z;
        a.w += v0.w + v1.w + v2.w + v3.w;
    }
    for (; i < end; i++) {
        float4 v = xv[d_csr_src[i]];
        a.x += v.x; a.y += v.y; a.z += v.z; a.w += v.w;
    }
    ((float4*)d_agg4)[n] = a;
}

// ---------------- layer 1 dense: K=4, smem-resident weights ----------------
__global__ void layer1_dense(const float* __restrict__ x,
                             const float* __restrict__ w_rel,
                             const float* __restrict__ b,
                             const float* __restrict__ w_root,
                             float* __restrict__ out) {
    __shared__ float wr[4][128], wo[4][128], bb[128];
    int t = threadIdx.x;  // 256
    if (t < 128) bb[t] = b[t];
    for (int i = t; i < 512; i += 256) {
        wr[i >> 7][i & 127] = w_rel[i];
        wo[i >> 7][i & 127] = w_root[i];
    }
    __syncthreads();
    int n = blockIdx.x * 2 + (t >> 7);
    int j = t & 127;
    if (n >= NN) return;
    float4 a  = ((const float4*)d_agg4)[n];
    float4 xx = ((const float4*)x)[n];
    float acc = bb[j]
              + a.x  * wr[0][j] + a.y  * wr[1][j] + a.z  * wr[2][j] + a.w  * wr[3][j]
              + xx.x * wo[0][j] + xx.y * wo[1][j] + xx.z * wo[2][j] + xx.w * wo[3][j];
    out[n * D + j] = fmaxf(acc, 0.f);
}

// ---------------- 128-dim aggregation: one warp per node, no atomics ----------------
__global__ void agg128(const float* __restrict__ h, float* __restrict__ agg) {
    int warp = (blockIdx.x * blockDim.x + threadIdx.x) >> 5;
    int lane = threadIdx.x & 31;
    if (warp >= NN) return;
    int beg = d_rowptr[warp], end = d_rowptr[warp + 1];
    const float4* hv = (const float4*)h;
    float4 acc = {0.f, 0.f, 0.f, 0.f};
    int i = beg;
    for (; i + 3 < end; i += 4) {
        int s0 = d_csr_src[i], s1 = d_csr_src[i + 1], s2 = d_csr_src[i + 2], s3 = d_csr_src[i + 3];
        float4 v0 = hv[s0 * 32 + lane];
        float4 v1 = hv[s1 * 32 + lane];
        float4 v2 = hv[s2 * 32 + lane];
        float4 v3 = hv[s3 * 32 + lane];
        acc.x += v0.x + v1.x + v2.x + v3.x;
        acc.y += v0.y + v1.y + v2.y + v3.y;
        acc.z += v0.z + v1.z + v2.z + v3.z;
        acc.w += v0.w + v1.w + v2.w + v3.w;
    }
    for (; i < end; i++) {
        float4 v = hv[d_csr_src[i] * 32 + lane];
        acc.x += v.x; acc.y += v.y; acc.z += v.z; acc.w += v.w;
    }
    ((float4*)agg)[warp * 32 + lane] = acc;
}

// ---------------- fused GEMM: out = relu([agg|h] @ [w_rel; w_root] + b) ----------------
// BM=128, BN=128, BK=16, 256 threads, 8x8 microtile per thread.
__global__ void gemm_fused(const float* __restrict__ agg, const float* __restrict__ h,
                           const float* __restrict__ w_rel, const float* __restrict__ w_root,
                           const float* __restrict__ bias, float* __restrict__ out, int M) {
    __shared__ float As[16][132];  // padded: 2-way max conflict on stores, aligned micro-loads
    __shared__ float Bs[16][128];
    int tid = threadIdx.x;
    int block_m = blockIdx.x * 128;
    int tm = (tid >> 4) * 8;
    int tn = (tid & 15) * 8;
    float acc[8][8];
#pragma unroll
    for (int i = 0; i < 8; i++)
#pragma unroll
        for (int j = 0; j < 8; j++) acc[i][j] = 0.f;

    for (int k0 = 0; k0 < 256; k0 += 16) {
        const float* Asrc = (k0 < 128) ? agg : h;
        const float* Bsrc = (k0 < 128) ? w_rel : w_root;
        int kbase = k0 & 127;
        // load A tile 128x16 (float4 per thread x2)
        {
            int r  = tid >> 2;
            int c4 = (tid & 3) * 4;
#pragma unroll
            for (int rr = 0; rr < 128; rr += 64) {
                int row = block_m + r + rr;
                float4 v = {0.f, 0.f, 0.f, 0.f};
                if (row < M) v = *(const float4*)(Asrc + (size_t)row * D + kbase + c4);
                As[c4 + 0][r + rr] = v.x;
                As[c4 + 1][r + rr] = v.y;
                As[c4 + 2][r + rr] = v.z;
                As[c4 + 3][r + rr] = v.w;
            }
        }
        // load B tile 16x128
        {
            int br = tid >> 5;
            int bc = (tid & 31) * 4;
#pragma unroll
            for (int rr = 0; rr < 16; rr += 8) {
                float4 v = *(const float4*)(Bsrc + (size_t)(kbase + br + rr) * D + bc);
                *(float4*)&Bs[br + rr][bc] = v;
            }
        }
        __syncthreads();
#pragma unroll
        for (int k = 0; k < 16; k++) {
            float a[8], b[8];
#pragma unroll
            for (int i = 0; i < 8; i++) a[i] = As[k][tm + i];
#pragma unroll
            for (int j = 0; j < 8; j++) b[j] = Bs[k][tn + j];
#pragma unroll
            for (int i = 0; i < 8; i++)
#pragma unroll
                for (int j = 0; j < 8; j++) acc[i][j] += a[i] * b[j];
        }
        __syncthreads();
    }
    // epilogue: +bias, relu, store
#pragma unroll
    for (int i = 0; i < 8; i++) {
        int row = block_m + tm + i;
        if (row >= M) continue;
#pragma unroll
        for (int j = 0; j < 8; j += 4) {
            float4 v;
            v.x = fmaxf(acc[i][j + 0] + bias[tn + j + 0], 0.f);
            v.y = fmaxf(acc[i][j + 1] + bias[tn + j + 1], 0.f);
            v.z = fmaxf(acc[i][j + 2] + bias[tn + j + 2], 0.f);
            v.w = fmaxf(acc[i][j + 3] + bias[tn + j + 3], 0.f);
            *(float4*)(out + (size_t)row * D + tn + j) = v;
        }
    }
}

// ---------------- pooling: run-length reduction over sorted batch ----------------
__global__ void pool_k(const float* __restrict__ h, const int* __restrict__ batch) {
    __shared__ int gb[POOL_CHUNK];
    int j = threadIdx.x;  // 128
    int n0 = blockIdx.x * POOL_CHUNK;
    int n1 = n0 + POOL_CHUNK; if (n1 > NN) n1 = NN;
    for (int k = j; k < n1 - n0; k += 128) gb[k] = batch[n0 + k];
    __syncthreads();
    float s = 0.f, m = 0.f;
    int cnt = 0;
    int cur = gb[0];
    for (int n = n0; n < n1; n++) {
        int g = gb[n - n0];
        if (g != cur) {
            atomicAdd(&d_pool_sum[cur * D + j], s);
            atomicMax((int*)&d_pool_max[cur * D + j], __float_as_int(m));
            if (j == 0) atomicAdd(&d_pool_cnt[cur], cnt);
            s = 0.f; m = 0.f; cnt = 0; cur = g;
        }
        float v = h[(size_t)n * D + j];
        s += v;
        m = fmaxf(m, v);
        cnt++;
    }
    atomicAdd(&d_pool_sum[cur * D + j], s);
    atomicMax((int*)&d_pool_max[cur * D + j], __float_as_int(m));
    if (j == 0) atomicAdd(&d_pool_cnt[cur], cnt);
}

// ---------------- head: [max|mean|m] @ fc -> relu -> fc2 ----------------
__global__ void head_k(const float* __restrict__ metadata,
                       const float* __restrict__ convm_w, const float* __restrict__ convm_b,
                       const float* __restrict__ fc_w, const float* __restrict__ fc_b,
                       const float* __restrict__ fc2_w, const float* __restrict__ fc2_b,
                       float* __restrict__ out) {
    int g = blockIdx.x;
    int j = threadIdx.x;  // 128
    __shared__ float xc[260];
    __shared__ float red[128];
    float inv = 1.f / fmaxf((float)d_pool_cnt[g], 1.f);
    xc[j]       = d_pool_max[g * D + j];
    xc[128 + j] = d_pool_sum[g * D + j] * inv;
    if (j < 4) xc[256 + j] = fmaxf(metadata[g] * convm_w[j] + convm_b[j], 0.f);
    __syncthreads();
    float acc = fc_b[j];
#pragma unroll 4
    for (int k = 0; k < 260; k++) acc += xc[k] * fc_w[k * D + j];
    red[j] = fmaxf(acc, 0.f) * fc2_w[j];
    __syncthreads();
    for (int off = 64; off > 0; off >>= 1) {
        if (j < off) red[j] += red[j + off];
        __syncthreads();
    }
    if (j == 0) out[g] = red[0] + fc2_b[0];
}

// ---------------- launch ----------------
extern "C" void kernel_launch(void* const* d_in, const int* in_sizes, int n_in,
                              void* d_out, int out_size) {
    const float* x        = (const float*)d_in[0];
    const float* metadata = (const float*)d_in[1];
    const int*   ei       = (const int*)d_in[2];
    const int*   batch    = (const int*)d_in[3];
    const float* w_rel1 = (const float*)d_in[4];
    const float* b_rel1 = (const float*)d_in[5];
    const float* w_root1= (const float*)d_in[6];
    const float* w_rel2 = (const float*)d_in[7];
    const float* b_rel2 = (const float*)d_in[8];
    const float* w_root2= (const float*)d_in[9];
    const float* w_rel3 = (const float*)d_in[10];
    const float* b_rel3 = (const float*)d_in[11];
    const float* w_root3= (const float*)d_in[12];
    const float* w_rel4 = (const float*)d_in[13];
    const float* b_rel4 = (const float*)d_in[14];
    const float* w_root4= (const float*)d_in[15];
    const float* convm_w= (const float*)d_in[16];
    const float* convm_b= (const float*)d_in[17];
    const float* fc_w   = (const float*)d_in[18];
    const float* fc_b   = (const float*)d_in[19];
    const float* fc2_w  = (const float*)d_in[20];
    const float* fc2_b  = (const float*)d_in[21];
    float* out = (float*)d_out;

    const int* srcp = ei;
    const int* dstp = ei + NE;

    // resolve device-global addresses (host side needs symbol addresses only for args-by-symbol; kernels use them directly)
    zero_prep<<<512, 256>>>();
    count_k<<<2048, 256>>>(dstp);
    scan_rowptr<<<1, 1024>>>();
    copy_cursor<<<512, 256>>>();
    scatter_k<<<2048, 256>>>(srcp, dstp);

    // layer 1 (K=4)
    agg4_k<<<(NN + 255) / 256, 256>>>(x);
    layer1_dense<<<(NN + 1) / 2, 256>>>(x, w_rel1, b_rel1, w_root1, d_hA);

    const int gemm_grid = (NN + 127) / 128;

    // layer 2
    agg128<<<(NN + 7) / 8, 256>>>(d_hA, d_agg);
    gemm_fused<<<gemm_grid, 256>>>(d_agg, d_hA, w_rel2, w_root2, b_rel2, d_hB, NN);
    // layer 3
    agg128<<<(NN + 7) / 8, 256>>>(d_hB, d_agg);
    gemm_fused<<<gemm_grid, 256>>>(d_agg, d_hB, w_rel3, w_root3, b_rel3, d_hA, NN);
    // layer 4
    agg128<<<(NN + 7) / 8, 256>>>(d_hA, d_agg);
    gemm_fused<<<gemm_grid, 256>>>(d_agg, d_hA, w_rel4, w_root4, b_rel4, d_hB, NN);

    // pooling + head
    pool_k<<<(NN + POOL_CHUNK - 1) / POOL_CHUNK, 128>>>(d_hB, batch);
    head_k<<<NG, 128>>>(metadata, convm_w, convm_b, fc_w, fc_b, fc2_w, fc2_b, out);
}